// round 16
// baseline (speedup 1.0000x reference)
#include <cuda_runtime.h>
#include <cuda_fp16.h>
#include <cstdint>

// Problem constants
#define Bsz 4
#define Ssz 2048
#define Hn  16
#define DKk 64
#define Dm  1024
#define Mrows (Bsz*Ssz)   // 8192

#define NPERS 304   // persistent CTAs (2 per SM on 152-SM GB300)

// ---------------- scratch (__device__ globals, fp16) ------------------------
__device__ __align__(1024) __half g_Xq[(size_t)Mrows*Dm];
__device__ __align__(1024) __half g_Xk[(size_t)Mrows*Dm];
__device__ __align__(1024) __half g_Xv[(size_t)Mrows*Dm];
__device__ __align__(1024) __half g_Wq[(size_t)Dm*Dm];
__device__ __align__(1024) __half g_Wk[(size_t)Dm*Dm];
__device__ __align__(1024) __half g_Wv[(size_t)Dm*Dm];
__device__ __align__(1024) __half g_Wo[(size_t)Dm*Dm];
__device__ __align__(1024) __half g_Q[(size_t)Bsz*Hn*Ssz*DKk];    // [b,h,s,d], pre-scaled log2e/8
__device__ __align__(1024) __half g_K[(size_t)Bsz*Hn*Ssz*DKk];    // [b,h,s,d]
__device__ __align__(1024) __half g_Vt[(size_t)Bsz*Hn*DKk*Ssz];   // [b,h,d,s]  TRANSPOSED
__device__ __align__(1024) __half g_attn[(size_t)Mrows*Dm];       // [B*S, D]
__device__ unsigned g_ctr[3];

__global__ void reset_ctrs() { if (threadIdx.x < 3) g_ctr[threadIdx.x] = 0; }

// ---------------- helpers ----------------------------------------------------
__device__ __forceinline__ uint32_t smem_u32(const void* p) {
    uint32_t a;
    asm("{ .reg .u64 t; cvta.to.shared.u64 t, %1; cvt.u32.u64 %0, t; }" : "=r"(a) : "l"(p));
    return a;
}
__device__ __forceinline__ void cp_async16(uint32_t dst, const void* src) {
    asm volatile("cp.async.cg.shared.global [%0], [%1], 16;" :: "r"(dst), "l"(src));
}
#define CP_COMMIT() asm volatile("cp.async.commit_group;" ::: "memory")
#define CP_WAIT0()  asm volatile("cp.async.wait_group 0;" ::: "memory")

__device__ __forceinline__ void mma_f16(float* c, const uint32_t* a, uint32_t b0, uint32_t b1) {
    asm volatile(
        "mma.sync.aligned.m16n8k16.row.col.f32.f16.f16.f32 "
        "{%0,%1,%2,%3}, {%4,%5,%6,%7}, {%8,%9}, {%0,%1,%2,%3};"
        : "+f"(c[0]), "+f"(c[1]), "+f"(c[2]), "+f"(c[3])
        : "r"(a[0]), "r"(a[1]), "r"(a[2]), "r"(a[3]), "r"(b0), "r"(b1));
}
// f16-accumulator HMMA: D/C are 2 packed-half2 regs (row g, row g+8)
__device__ __forceinline__ void mma_f16h(uint32_t* c, const uint32_t* a, uint32_t b0, uint32_t b1) {
    asm volatile(
        "mma.sync.aligned.m16n8k16.row.col.f16.f16.f16.f16 "
        "{%0,%1}, {%2,%3,%4,%5}, {%6,%7}, {%0,%1};"
        : "+r"(c[0]), "+r"(c[1])
        : "r"(a[0]), "r"(a[1]), "r"(a[2]), "r"(a[3]), "r"(b0), "r"(b1));
}
__device__ __forceinline__ void ldsm4(uint32_t* r, uint32_t addr) {
    asm volatile("ldmatrix.sync.aligned.m8n8.x4.shared.b16 {%0,%1,%2,%3}, [%4];"
        : "=r"(r[0]), "=r"(r[1]), "=r"(r[2]), "=r"(r[3]) : "r"(addr));
}
__device__ __forceinline__ __half2 u2h(uint32_t u) { return *(__half2*)&u; }
__device__ __forceinline__ uint32_t packh2(float a, float b) {
    __half2 h = __floats2half2_rn(a, b);
    return *(uint32_t*)&h;
}

// ---------------------------------------------------------------------------
// fp16 NT GEMM tile body (R13 form): K-chunk 64 (NT=16), 2-stage cp.async.
// ---------------------------------------------------------------------------
#define LDW 72
#define GBUF (128 * LDW)
#define GEMM_SMEM_BYTES (4 * GBUF * 2)    // 73728 B

__device__ __forceinline__ void gemm_tile(const __half* __restrict__ X,
                                          const __half* __restrict__ W,
                                          const float* __restrict__ bias,
                                          void* __restrict__ outp,
                                          int mode, int bm, int bn)
{
    extern __shared__ __half smh[];
    __half* Abuf[2] = { smh,            smh + GBUF };
    __half* Bbuf[2] = { smh + 2*GBUF,   smh + 3*GBUF };

    const int tid  = threadIdx.x;
    const int lane = tid & 31, wid = tid >> 5;
    const int wm   = wid >> 2, wn = wid & 3;
    const int g    = lane >> 2, q = lane & 3;

    const int lrow16 = lane & 15;
    const int lhi    = lane >> 4;
    const int bsub   = lane & 7;
    const int bhi8   = (lane >> 3) & 1;
    const int bnt    = lane >> 4;

    uint32_t abase[2], bbase[2];
    {
        uint32_t aoff = ((wm*64 + lrow16) * LDW + lhi*8) * 2;
        uint32_t boff = ((wn*32 + bnt*8 + bsub) * LDW + bhi8*8) * 2;
#pragma unroll
        for (int s = 0; s < 2; s++) {
            abase[s] = smem_u32(Abuf[s]) + aoff;
            bbase[s] = smem_u32(Bbuf[s]) + boff;
        }
    }

    float acc[4][4][4];
#pragma unroll
    for (int i = 0; i < 4; i++)
#pragma unroll
        for (int j = 0; j < 4; j++)
#pragma unroll
            for (int k = 0; k < 4; k++) acc[i][j][k] = 0.f;

    auto issue_tile = [&](int kt, int buf) {
#pragma unroll
        for (int i = 0; i < 4; i++) {
            int idx = i * 256 + tid;
            int r = idx >> 3, c = idx & 7;
            cp_async16(smem_u32(&Abuf[buf][r * LDW + c * 8]),
                       X + (size_t)(bm + r) * Dm + kt * 64 + c * 8);
        }
#pragma unroll
        for (int i = 0; i < 4; i++) {
            int idx = i * 256 + tid;
            int r = idx >> 3, c = idx & 7;
            cp_async16(smem_u32(&Bbuf[buf][r * LDW + c * 8]),
                       W + (size_t)(bn + r) * Dm + kt * 64 + c * 8);
        }
        CP_COMMIT();
    };

    const int NT = Dm / 64;
    issue_tile(0, 0);

    for (int kt = 0; kt < NT; kt++) {
        const int buf = kt & 1;
        CP_WAIT0();
        __syncthreads();
        if (kt + 1 < NT) issue_tile(kt + 1, buf ^ 1);

        uint32_t ab = abase[buf], bb_ = bbase[buf];
#pragma unroll
        for (int kk = 0; kk < 4; kk++) {
            uint32_t afr[4][4], bfr[2][4];
#pragma unroll
            for (int mt = 0; mt < 4; mt++)
                ldsm4(afr[mt], ab + kk*32 + mt * (16 * LDW * 2));
#pragma unroll
            for (int ntp = 0; ntp < 2; ntp++)
                ldsm4(bfr[ntp], bb_ + kk*32 + ntp * (16 * LDW * 2));
#pragma unroll
            for (int mt = 0; mt < 4; mt++)
#pragma unroll
                for (int nt = 0; nt < 4; nt++)
                    mma_f16(acc[mt][nt], afr[mt],
                            bfr[nt >> 1][(nt & 1) * 2], bfr[nt >> 1][(nt & 1) * 2 + 1]);
        }
    }
    __syncthreads();

#pragma unroll
    for (int mt = 0; mt < 4; mt++) {
        int r0 = bm + wm * 64 + mt * 16 + g;
        int r1 = r0 + 8;
#pragma unroll
        for (int nt = 0; nt < 4; nt++) {
            int n = bn + wn * 32 + nt * 8 + q * 2;
            float bn0 = bias[n], bn1 = bias[n + 1];
            float c0 = acc[mt][nt][0] + bn0, c1 = acc[mt][nt][1] + bn1;
            float c2 = acc[mt][nt][2] + bn0, c3 = acc[mt][nt][3] + bn1;
            if (mode == 0) {
                float* fo = (float*)outp;
                *(float2*)&fo[(size_t)r0 * Dm + n] = make_float2(c0, c1);
                *(float2*)&fo[(size_t)r1 * Dm + n] = make_float2(c2, c3);
            } else if (mode == 3) {
                int h = n >> 6, d = n & 63;
                int b0i = r0 >> 11, s0 = r0 & (Ssz - 1);
                int b1i = r1 >> 11, s1 = r1 & (Ssz - 1);
                __half* vo = (__half*)outp;
                vo[((size_t)((b0i*Hn + h)*DKk + d    ))*Ssz + s0] = __float2half_rn(c0);
                vo[((size_t)((b0i*Hn + h)*DKk + d + 1))*Ssz + s0] = __float2half_rn(c1);
                vo[((size_t)((b1i*Hn + h)*DKk + d    ))*Ssz + s1] = __float2half_rn(c2);
                vo[((size_t)((b1i*Hn + h)*DKk + d + 1))*Ssz + s1] = __float2half_rn(c3);
            } else {
                float sc = (mode == 1) ? (0.125f * 1.4426950408889634f) : 1.0f;
                int h = n >> 6, d = n & 63;
                int b0i = r0 >> 11, s0 = r0 & (Ssz - 1);
                int b1i = r1 >> 11, s1 = r1 & (Ssz - 1);
                __half* ho = (__half*)outp;
                *(__half2*)&ho[((size_t)((b0i*Hn + h)*Ssz + s0))*DKk + d] =
                    __floats2half2_rn(c0 * sc, c1 * sc);
                *(__half2*)&ho[((size_t)((b1i*Hn + h)*Ssz + s1))*DKk + d] =
                    __floats2half2_rn(c2 * sc, c3 * sc);
            }
        }
    }
}

__global__ __launch_bounds__(256, 2) void gemm_qkv_f16(const float* __restrict__ bq,
                                                       const float* __restrict__ bk,
                                                       const float* __restrict__ bv)
{
    __shared__ unsigned s_item;
    for (;;) {
        if (threadIdx.x == 0) s_item = atomicAdd(&g_ctr[0], 1);
        __syncthreads();
        unsigned item = s_item;
        if (item >= 1536) break;
        int z = item >> 9;
        int t = item & 511;
        int bn = (t & 7) << 7;
        int bm = (t >> 3) << 7;
        if (z == 0)      gemm_tile(g_Xq, g_Wq, bq, g_Q,  1, bm, bn);
        else if (z == 1) gemm_tile(g_Xk, g_Wk, bk, g_K,  2, bm, bn);
        else             gemm_tile(g_Xv, g_Wv, bv, g_Vt, 3, bm, bn);
    }
}

__global__ __launch_bounds__(256, 2) void gemm_out_f16(const float* __restrict__ bo,
                                                       float* __restrict__ out)
{
    __shared__ unsigned s_item;
    for (;;) {
        if (threadIdx.x == 0) s_item = atomicAdd(&g_ctr[2], 1);
        __syncthreads();
        unsigned item = s_item;
        if (item >= 512) break;
        int bn = (item & 7) << 7;
        int bm = (item >> 3) << 7;
        gemm_tile(g_attn, g_Wo, bo, out, 0, bm, bn);
    }
}

// ---------------------------------------------------------------------------
// f32 -> fp16 RN conversion of GEMM inputs
// ---------------------------------------------------------------------------
__global__ __launch_bounds__(256) void conv_x3(const float* __restrict__ xq,
                                               const float* __restrict__ xk,
                                               const float* __restrict__ xv)
{
    const float* s; __half* d;
    if (blockIdx.z == 0)      { s = xq; d = g_Xq; }
    else if (blockIdx.z == 1) { s = xk; d = g_Xk; }
    else                      { s = xv; d = g_Xv; }
    int i = blockIdx.x * blockDim.x + threadIdx.x;
    float4 v = ((const float4*)s)[i];
    __half2 h0 = __floats2half2_rn(v.x, v.y);
    __half2 h1 = __floats2half2_rn(v.z, v.w);
    uint2 o = { *(uint32_t*)&h0, *(uint32_t*)&h1 };
    *(uint2*)&d[(size_t)i * 4] = o;
}

__global__ __launch_bounds__(256) void conv_w4(const float* __restrict__ wq,
                                               const float* __restrict__ wk,
                                               const float* __restrict__ wv,
                                               const float* __restrict__ wo)
{
    const float* s; __half* d;
    if (blockIdx.z == 0)      { s = wq; d = g_Wq; }
    else if (blockIdx.z == 1) { s = wk; d = g_Wk; }
    else if (blockIdx.z == 2) { s = wv; d = g_Wv; }
    else                      { s = wo; d = g_Wo; }
    int i = blockIdx.x * blockDim.x + threadIdx.x;
    float4 v = ((const float4*)s)[i];
    __half2 h0 = __floats2half2_rn(v.x, v.y);
    __half2 h1 = __floats2half2_rn(v.z, v.w);
    uint2 o = { *(uint32_t*)&h0, *(uint32_t*)&h1 };
    *(uint2*)&d[(size_t)i * 4] = o;
}

// ---------------------------------------------------------------------------
// Flash attention: QK via TWO split-K f16-accum chains (K 0..31, 32..63)
// combined in f32 (shorter rounding chains); softmax on f32 with exp2f
// (accuracy margin recovered); PV f32 accum.
// ---------------------------------------------------------------------------
#define LDKH 72
#define KTILE_H (64 * LDKH)
#define ATT_SMEM (4 * KTILE_H * 2)   // K x2, V x2 = 36864 B

__global__ __launch_bounds__(256, 2) void attn_f16_kernel()
{
    extern __shared__ __half smh[];
    __half* Kbuf[2] = { smh,               smh + KTILE_H };
    __half* Vbuf[2] = { smh + 2*KTILE_H,   smh + 3*KTILE_H };
    __shared__ unsigned s_item;

    const int tid = threadIdx.x;
    const int lane = tid & 31, w = tid >> 5;

    const int lrow16 = lane & 15;
    const int lhi    = lane >> 4;
    const int bsub   = lane & 7;
    const int bhi8   = (lane >> 3) & 1;
    const int bnt    = lane >> 4;

    uint32_t kfb[2], vfb[2];
    {
        uint32_t b0 = smem_u32(smh);
        uint32_t off = ((bnt*8 + bsub) * LDKH + bhi8*8) * 2;
        kfb[0] = b0 + off;
        kfb[1] = b0 + KTILE_H*2 + off;
        vfb[0] = b0 + 2*KTILE_H*2 + off;
        vfb[1] = b0 + 3*KTILE_H*2 + off;
    }
    const uint32_t qfrag_addr = smem_u32(smh) + ((w*16 + lrow16) * LDKH + lhi*8) * 2;

    for (;;) {
        if (tid == 0) s_item = atomicAdd(&g_ctr[1], 1);
        __syncthreads();
        unsigned item = s_item;
        if (item >= 1024) break;
        const int bh = item >> 4;
        const int qb = (item & 15) << 7;

        const __half* Qb  = g_Q  + (size_t)bh * Ssz * DKk;
        const __half* Kbp = g_K  + (size_t)bh * Ssz * DKk;
        const __half* Vtp = g_Vt + (size_t)bh * DKk * Ssz;

#pragma unroll
        for (int i = 0; i < 4; i++) {
            int idx = i * 256 + tid;
            int r = idx >> 3, c = idx & 7;
            cp_async16(smem_u32(&smh[r * LDKH + c * 8]),
                       Qb + (size_t)(qb + r) * DKk + c * 8);
        }
        CP_COMMIT();
        CP_WAIT0();
        __syncthreads();

        uint32_t qfr[4][4];
#pragma unroll
        for (int kk = 0; kk < 4; kk++)
            ldsm4(qfr[kk], qfrag_addr + kk*32);
        __syncthreads();

        auto issue_kv = [&](int kt, int bufi) {
            const int base = kt * 64;
            __half* kd = Kbuf[bufi];
            __half* vd = Vbuf[bufi];
#pragma unroll
            for (int i = 0; i < 2; i++) {
                int idx = i * 256 + tid;
                int r = idx >> 3, c = idx & 7;
                cp_async16(smem_u32(&kd[r * LDKH + c * 8]),
                           Kbp + (size_t)(base + r) * DKk + c * 8);
                cp_async16(smem_u32(&vd[r * LDKH + c * 8]),
                           Vtp + (size_t)r * Ssz + base + c * 8);
            }
            CP_COMMIT();
        };

        float oacc[8][4];
#pragma unroll
        for (int nt = 0; nt < 8; nt++)
#pragma unroll
            for (int k = 0; k < 4; k++) oacc[nt][k] = 0.f;
        float mA = -1e30f, mB = -1e30f, lA = 0.f, lB = 0.f;

        const int NT = Ssz / 64;
        issue_kv(0, 0);

        for (int kt = 0; kt < NT; kt++) {
            const int buf = kt & 1;
            CP_WAIT0();
            __syncthreads();
            if (kt + 1 < NT) issue_kv(kt + 1, buf ^ 1);

            // ---- S = Q K^T : two split-K f16-accum chains ----
            uint32_t sa[8][2], sb[8][2];
#pragma unroll
            for (int nt = 0; nt < 8; nt++) {
                sa[nt][0] = 0u; sa[nt][1] = 0u;
                sb[nt][0] = 0u; sb[nt][1] = 0u;
            }
            uint32_t kb = kfb[buf];
#pragma unroll
            for (int ntp = 0; ntp < 4; ntp++) {
#pragma unroll
                for (int kk = 0; kk < 4; kk++) {
                    uint32_t bb[4];
                    ldsm4(bb, kb + ntp * (16 * LDKH * 2) + kk * 32);
                    if (kk < 2) {
                        mma_f16h(sa[2*ntp],     qfr[kk], bb[0], bb[1]);
                        mma_f16h(sa[2*ntp + 1], qfr[kk], bb[2], bb[3]);
                    } else {
                        mma_f16h(sb[2*ntp],     qfr[kk], bb[0], bb[1]);
                        mma_f16h(sb[2*ntp + 1], qfr[kk], bb[2], bb[3]);
                    }
                }
            }

            // ---- combine halves in f32 ----
            float sacc[8][4];
#pragma unroll
            for (int nt = 0; nt < 8; nt++) {
                float2 a0 = __half22float2(u2h(sa[nt][0]));
                float2 b0 = __half22float2(u2h(sb[nt][0]));
                float2 a1 = __half22float2(u2h(sa[nt][1]));
                float2 b1 = __half22float2(u2h(sb[nt][1]));
                sacc[nt][0] = a0.x + b0.x;
                sacc[nt][1] = a0.y + b0.y;
                sacc[nt][2] = a1.x + b1.x;
                sacc[nt][3] = a1.y + b1.y;
            }

            // ---- online softmax (f32 path, exp2f), skip-corr ----
            float mtA = -1e30f, mtB = -1e30f;
#pragma unroll
            for (int nt = 0; nt < 8; nt++) {
                mtA = fmaxf(mtA, fmaxf(sacc[nt][0], sacc[nt][1]));
                mtB = fmaxf(mtB, fmaxf(sacc[nt][2], sacc[nt][3]));
            }
            mtA = fmaxf(mtA, __shfl_xor_sync(0xffffffffu, mtA, 1));
            mtA = fmaxf(mtA, __shfl_xor_sync(0xffffffffu, mtA, 2));
            mtB = fmaxf(mtB, __shfl_xor_sync(0xffffffffu, mtB, 1));
            mtB = fmaxf(mtB, __shfl_xor_sync(0xffffffffu, mtB, 2));

            float corrA = 1.f, corrB = 1.f;
            if (mtA > mA || mtB > mB) {
                float mnA = fmaxf(mA, mtA), mnB = fmaxf(mB, mtB);
                corrA = exp2f(mA - mnA); corrB = exp2f(mB - mnB);
                mA = mnA; mB = mnB;
#pragma unroll
                for (int nt = 0; nt < 8; nt++) {
                    oacc[nt][0] *= corrA; oacc[nt][1] *= corrA;
                    oacc[nt][2] *= corrB; oacc[nt][3] *= corrB;
                }
            }

            float sA = 0.f, sB = 0.f;
            uint32_t pA[8], pB[8];
#pragma unroll
            for (int nt = 0; nt < 8; nt++) {
                float p0 = exp2f(sacc[nt][0] - mA);
                float p1 = exp2f(sacc[nt][1] - mA);
                float p2 = exp2f(sacc[nt][2] - mB);
                float p3 = exp2f(sacc[nt][3] - mB);
                sA += p0 + p1;
                sB += p2 + p3;
                pA[nt] = packh2(p0, p1);
                pB[nt] = packh2(p2, p3);
            }
            sA += __shfl_xor_sync(0xffffffffu, sA, 1);
            sA += __shfl_xor_sync(0xffffffffu, sA, 2);
            sB += __shfl_xor_sync(0xffffffffu, sB, 1);
            sB += __shfl_xor_sync(0xffffffffu, sB, 2);
            lA = lA * corrA + sA;
            lB = lB * corrB + sB;

            // ---- O += P * V (f32 accum) ----
            uint32_t vb = vfb[buf];
#pragma unroll
            for (int ntp = 0; ntp < 4; ntp++) {
#pragma unroll
                for (int kk = 0; kk < 4; kk++) {
                    uint32_t bb[4];
                    ldsm4(bb, vb + ntp * (16 * LDKH * 2) + kk * 32);
                    uint32_t afr[4] = { pA[2*kk], pB[2*kk], pA[2*kk + 1], pB[2*kk + 1] };
                    mma_f16(oacc[2*ntp],     afr, bb[0], bb[1]);
                    mma_f16(oacc[2*ntp + 1], afr, bb[2], bb[3]);
                }
            }
        }

        const int g = lane >> 2, q = lane & 3;
        float invA = 1.f / lA, invB = 1.f / lB;
        int b = bh >> 4, h = bh & 15;
        int row0 = qb + w * 16 + g;
        int row1 = row0 + 8;
#pragma unroll
        for (int nt = 0; nt < 8; nt++) {
            int col = h * DKk + nt * 8 + q * 2;
            *(__half2*)&g_attn[(size_t)(b * Ssz + row0) * Dm + col] =
                __floats2half2_rn(oacc[nt][0] * invA, oacc[nt][1] * invA);
            *(__half2*)&g_attn[(size_t)(b * Ssz + row1) * Dm + col] =
                __floats2half2_rn(oacc[nt][2] * invB, oacc[nt][3] * invB);
        }
    }
}

// ---------------------------------------------------------------------------
extern "C" void kernel_launch(void* const* d_in, const int* in_sizes, int n_in,
                              void* d_out, int out_size)
{
    const float* query = (const float*)d_in[0];
    const float* key_  = (const float*)d_in[1];
    const float* value = (const float*)d_in[2];
    const float* w_q   = (const float*)d_in[3];
    const float* b_q   = (const float*)d_in[4];
    const float* w_k   = (const float*)d_in[5];
    const float* b_k   = (const float*)d_in[6];
    const float* w_v   = (const float*)d_in[7];
    const float* b_v   = (const float*)d_in[8];
    const float* w_o   = (const float*)d_in[9];
    const float* b_o   = (const float*)d_in[10];
    float* out = (float*)d_out;

    cudaFuncSetAttribute(gemm_qkv_f16, cudaFuncAttributeMaxDynamicSharedMemorySize, GEMM_SMEM_BYTES);
    cudaFuncSetAttribute(gemm_out_f16, cudaFuncAttributeMaxDynamicSharedMemorySize, GEMM_SMEM_BYTES);
    cudaFuncSetAttribute(attn_f16_kernel, cudaFuncAttributeMaxDynamicSharedMemorySize, ATT_SMEM);

    const int nX4 = Mrows * Dm / 4;
    const int nW4 = Dm * Dm / 4;

    reset_ctrs<<<1, 32>>>();

    conv_x3<<<dim3(nX4 / 256, 1, 3), 256>>>(query, key_, value);
    conv_w4<<<dim3(nW4 / 256, 1, 4), 256>>>(w_q, w_k, w_v, w_o);

    gemm_qkv_f16<<<NPERS, 256, GEMM_SMEM_BYTES>>>(b_q, b_k, b_v);

    attn_f16_kernel<<<NPERS, 256, ATT_SMEM>>>();

    gemm_out_f16<<<NPERS, 256, GEMM_SMEM_BYTES>>>(b_o, out);
}

// round 17
// speedup vs baseline: 1.0778x; 1.0778x over previous
#include <cuda_runtime.h>
#include <cuda_fp16.h>
#include <cstdint>

// Problem constants
#define Bsz 4
#define Ssz 2048
#define Hn  16
#define DKk 64
#define Dm  1024
#define Mrows (Bsz*Ssz)   // 8192

#define NPERS 304   // persistent CTAs (2 per SM on 152-SM GB300); grid == residency

// ---------------- scratch (__device__ globals, fp16) ------------------------
__device__ __align__(1024) __half g_Xq[(size_t)Mrows*Dm];
__device__ __align__(1024) __half g_Xk[(size_t)Mrows*Dm];
__device__ __align__(1024) __half g_Xv[(size_t)Mrows*Dm];
__device__ __align__(1024) __half g_Wq[(size_t)Dm*Dm];
__device__ __align__(1024) __half g_Wk[(size_t)Dm*Dm];
__device__ __align__(1024) __half g_Wv[(size_t)Dm*Dm];
__device__ __align__(1024) __half g_Wo[(size_t)Dm*Dm];
__device__ __align__(1024) __half g_Q[(size_t)Bsz*Hn*Ssz*DKk];    // [b,h,s,d], pre-scaled log2e/8
__device__ __align__(1024) __half g_K[(size_t)Bsz*Hn*Ssz*DKk];    // [b,h,s,d]
__device__ __align__(1024) __half g_Vt[(size_t)Bsz*Hn*DKk*Ssz];   // [b,h,d,s]  TRANSPOSED
__device__ __align__(1024) __half g_attn[(size_t)Mrows*Dm];       // [B*S, D]
__device__ unsigned g_ctr[3];       // queues: 0=qkv(1536), 1=attn(1024), 2=out(512)
__device__ unsigned g_done_g[24];   // [z*8+nt] -> 64 when all m-tiles of that n-tile done
__device__ unsigned g_done_a[64];   // [b*16+qb16] -> 16 when all heads done

// ---------------- helpers ----------------------------------------------------
__device__ __forceinline__ uint32_t smem_u32(const void* p) {
    uint32_t a;
    asm("{ .reg .u64 t; cvta.to.shared.u64 t, %1; cvt.u32.u64 %0, t; }" : "=r"(a) : "l"(p));
    return a;
}
__device__ __forceinline__ void cp_async16(uint32_t dst, const void* src) {
    asm volatile("cp.async.cg.shared.global [%0], [%1], 16;" :: "r"(dst), "l"(src));
}
#define CP_COMMIT() asm volatile("cp.async.commit_group;" ::: "memory")
#define CP_WAIT0()  asm volatile("cp.async.wait_group 0;" ::: "memory")

__device__ __forceinline__ void mma_f16(float* c, const uint32_t* a, uint32_t b0, uint32_t b1) {
    asm volatile(
        "mma.sync.aligned.m16n8k16.row.col.f32.f16.f16.f32 "
        "{%0,%1,%2,%3}, {%4,%5,%6,%7}, {%8,%9}, {%0,%1,%2,%3};"
        : "+f"(c[0]), "+f"(c[1]), "+f"(c[2]), "+f"(c[3])
        : "r"(a[0]), "r"(a[1]), "r"(a[2]), "r"(a[3]), "r"(b0), "r"(b1));
}
__device__ __forceinline__ void ldsm4(uint32_t* r, uint32_t addr) {
    asm volatile("ldmatrix.sync.aligned.m8n8.x4.shared.b16 {%0,%1,%2,%3}, [%4];"
        : "=r"(r[0]), "=r"(r[1]), "=r"(r[2]), "=r"(r[3]) : "r"(addr));
}
__device__ __forceinline__ uint32_t packh2(float a, float b) {
    __half2 h = __floats2half2_rn(a, b);
    return *(uint32_t*)&h;
}

// ---------------------------------------------------------------------------
// fp16 NT GEMM tile body (R13 form, __noinline__ so one code copy serves
// both phases): 128x128 output tile, K-chunk 64, 2-stage cp.async.
// ---------------------------------------------------------------------------
#define LDW 72
#define GBUF (128 * LDW)
#define MEGA_SMEM_BYTES (4 * GBUF * 2)    // 73728 B (gemm layout; attn uses less)

__device__ __noinline__ void gemm_tile(const __half* __restrict__ X,
                                       const __half* __restrict__ W,
                                       const float* __restrict__ bias,
                                       void* __restrict__ outp,
                                       int mode, int bm, int bn)
{
    extern __shared__ __half smh[];
    __half* Abuf[2] = { smh,            smh + GBUF };
    __half* Bbuf[2] = { smh + 2*GBUF,   smh + 3*GBUF };

    const int tid  = threadIdx.x;
    const int lane = tid & 31, wid = tid >> 5;
    const int wm   = wid >> 2, wn = wid & 3;
    const int g    = lane >> 2, q = lane & 3;

    const int lrow16 = lane & 15;
    const int lhi    = lane >> 4;
    const int bsub   = lane & 7;
    const int bhi8   = (lane >> 3) & 1;
    const int bnt    = lane >> 4;

    uint32_t abase[2], bbase[2];
    {
        uint32_t aoff = ((wm*64 + lrow16) * LDW + lhi*8) * 2;
        uint32_t boff = ((wn*32 + bnt*8 + bsub) * LDW + bhi8*8) * 2;
#pragma unroll
        for (int s = 0; s < 2; s++) {
            abase[s] = smem_u32(Abuf[s]) + aoff;
            bbase[s] = smem_u32(Bbuf[s]) + boff;
        }
    }

    float acc[4][4][4];
#pragma unroll
    for (int i = 0; i < 4; i++)
#pragma unroll
        for (int j = 0; j < 4; j++)
#pragma unroll
            for (int k = 0; k < 4; k++) acc[i][j][k] = 0.f;

    auto issue_tile = [&](int kt, int buf) {
#pragma unroll
        for (int i = 0; i < 4; i++) {
            int idx = i * 256 + tid;
            int r = idx >> 3, c = idx & 7;
            cp_async16(smem_u32(&Abuf[buf][r * LDW + c * 8]),
                       X + (size_t)(bm + r) * Dm + kt * 64 + c * 8);
        }
#pragma unroll
        for (int i = 0; i < 4; i++) {
            int idx = i * 256 + tid;
            int r = idx >> 3, c = idx & 7;
            cp_async16(smem_u32(&Bbuf[buf][r * LDW + c * 8]),
                       W + (size_t)(bn + r) * Dm + kt * 64 + c * 8);
        }
        CP_COMMIT();
    };

    const int NT = Dm / 64;
    issue_tile(0, 0);

    for (int kt = 0; kt < NT; kt++) {
        const int buf = kt & 1;
        CP_WAIT0();
        __syncthreads();
        if (kt + 1 < NT) issue_tile(kt + 1, buf ^ 1);

        uint32_t ab = abase[buf], bb_ = bbase[buf];
#pragma unroll
        for (int kk = 0; kk < 4; kk++) {
            uint32_t afr[4][4], bfr[2][4];
#pragma unroll
            for (int mt = 0; mt < 4; mt++)
                ldsm4(afr[mt], ab + kk*32 + mt * (16 * LDW * 2));
#pragma unroll
            for (int ntp = 0; ntp < 2; ntp++)
                ldsm4(bfr[ntp], bb_ + kk*32 + ntp * (16 * LDW * 2));
#pragma unroll
            for (int mt = 0; mt < 4; mt++)
#pragma unroll
                for (int nt = 0; nt < 4; nt++)
                    mma_f16(acc[mt][nt], afr[mt],
                            bfr[nt >> 1][(nt & 1) * 2], bfr[nt >> 1][(nt & 1) * 2 + 1]);
        }
    }
    __syncthreads();

#pragma unroll
    for (int mt = 0; mt < 4; mt++) {
        int r0 = bm + wm * 64 + mt * 16 + g;
        int r1 = r0 + 8;
#pragma unroll
        for (int nt = 0; nt < 4; nt++) {
            int n = bn + wn * 32 + nt * 8 + q * 2;
            float bn0 = bias[n], bn1 = bias[n + 1];
            float c0 = acc[mt][nt][0] + bn0, c1 = acc[mt][nt][1] + bn1;
            float c2 = acc[mt][nt][2] + bn0, c3 = acc[mt][nt][3] + bn1;
            if (mode == 0) {
                float* fo = (float*)outp;
                *(float2*)&fo[(size_t)r0 * Dm + n] = make_float2(c0, c1);
                *(float2*)&fo[(size_t)r1 * Dm + n] = make_float2(c2, c3);
            } else if (mode == 3) {
                int h = n >> 6, d = n & 63;
                int b0i = r0 >> 11, s0 = r0 & (Ssz - 1);
                int b1i = r1 >> 11, s1 = r1 & (Ssz - 1);
                __half* vo = (__half*)outp;
                vo[((size_t)((b0i*Hn + h)*DKk + d    ))*Ssz + s0] = __float2half_rn(c0);
                vo[((size_t)((b0i*Hn + h)*DKk + d + 1))*Ssz + s0] = __float2half_rn(c1);
                vo[((size_t)((b1i*Hn + h)*DKk + d    ))*Ssz + s1] = __float2half_rn(c2);
                vo[((size_t)((b1i*Hn + h)*DKk + d + 1))*Ssz + s1] = __float2half_rn(c3);
            } else {
                float sc = (mode == 1) ? (0.125f * 1.4426950408889634f) : 1.0f;
                int h = n >> 6, d = n & 63;
                int b0i = r0 >> 11, s0 = r0 & (Ssz - 1);
                int b1i = r1 >> 11, s1 = r1 & (Ssz - 1);
                __half* ho = (__half*)outp;
                *(__half2*)&ho[((size_t)((b0i*Hn + h)*Ssz + s0))*DKk + d] =
                    __floats2half2_rn(c0 * sc, c1 * sc);
                *(__half2*)&ho[((size_t)((b1i*Hn + h)*Ssz + s1))*DKk + d] =
                    __floats2half2_rn(c2 * sc, c3 * sc);
            }
        }
    }
}

// ---------------------------------------------------------------------------
// f32 -> fp16 conversions (conv_x3 also resets the megakernel's counters)
// ---------------------------------------------------------------------------
__global__ __launch_bounds__(256) void conv_x3(const float* __restrict__ xq,
                                               const float* __restrict__ xk,
                                               const float* __restrict__ xv)
{
    if (blockIdx.x == 0 && blockIdx.z == 0) {
        int t = threadIdx.x;
        if (t < 3)                 g_ctr[t] = 0;
        else if (t >= 32 && t < 56)  g_done_g[t - 32] = 0;
        else if (t >= 64 && t < 128) g_done_a[t - 64] = 0;
    }
    const float* s; __half* d;
    if (blockIdx.z == 0)      { s = xq; d = g_Xq; }
    else if (blockIdx.z == 1) { s = xk; d = g_Xk; }
    else                      { s = xv; d = g_Xv; }
    int i = blockIdx.x * blockDim.x + threadIdx.x;
    float4 v = ((const float4*)s)[i];
    __half2 h0 = __floats2half2_rn(v.x, v.y);
    __half2 h1 = __floats2half2_rn(v.z, v.w);
    uint2 o = { *(uint32_t*)&h0, *(uint32_t*)&h1 };
    *(uint2*)&d[(size_t)i * 4] = o;
}

__global__ __launch_bounds__(256) void conv_w4(const float* __restrict__ wq,
                                               const float* __restrict__ wk,
                                               const float* __restrict__ wv,
                                               const float* __restrict__ wo)
{
    const float* s; __half* d;
    if (blockIdx.z == 0)      { s = wq; d = g_Wq; }
    else if (blockIdx.z == 1) { s = wk; d = g_Wk; }
    else if (blockIdx.z == 2) { s = wv; d = g_Wv; }
    else                      { s = wo; d = g_Wo; }
    int i = blockIdx.x * blockDim.x + threadIdx.x;
    float4 v = ((const float4*)s)[i];
    __half2 h0 = __floats2half2_rn(v.x, v.y);
    __half2 h1 = __floats2half2_rn(v.z, v.w);
    uint2 o = { *(uint32_t*)&h0, *(uint32_t*)&h1 };
    *(uint2*)&d[(size_t)i * 4] = o;
}

// ---------------------------------------------------------------------------
// MEGAKERNEL: qkv GEMMs -> flash attention -> out-proj, one persistent launch.
// All 304 CTAs are co-resident; cross-phase deps via fence+flag spin-waits.
// Attention math identical to R13 (rel_err check: 0.0007895642).
// ---------------------------------------------------------------------------
#define LDKH 72
#define KTILE_H (64 * LDKH)

__global__ __launch_bounds__(256, 2) void mega_kernel(const float* __restrict__ bq,
                                                      const float* __restrict__ bk,
                                                      const float* __restrict__ bv,
                                                      const float* __restrict__ bo,
                                                      float* __restrict__ out)
{
    extern __shared__ __half smh[];
    __shared__ unsigned s_item;
    const int tid = threadIdx.x;

    // ================= phase 1: QKV GEMMs (nt-major order) =================
    for (;;) {
        if (tid == 0) s_item = atomicAdd(&g_ctr[0], 1);
        __syncthreads();
        unsigned item = s_item;
        if (item >= 1536) break;
        int nt  = item / 192;
        int rem = item - nt * 192;
        int z   = rem >> 6;
        int mt  = rem & 63;
        int bm = mt << 7, bn = nt << 7;
        if (z == 0)      gemm_tile(g_Xq, g_Wq, bq, g_Q,  1, bm, bn);
        else if (z == 1) gemm_tile(g_Xk, g_Wk, bk, g_K,  2, bm, bn);
        else             gemm_tile(g_Xv, g_Wv, bv, g_Vt, 3, bm, bn);
        __threadfence();
        __syncthreads();
        if (tid == 0) atomicAdd(&g_done_g[z * 8 + nt], 1);
    }

    // ================= phase 2: flash attention (bq-major, h inner) ========
    {
        __half* Kbuf[2] = { smh,               smh + KTILE_H };
        __half* Vbuf[2] = { smh + 2*KTILE_H,   smh + 3*KTILE_H };

        const int lane = tid & 31, w = tid >> 5;
        const int lrow16 = lane & 15;
        const int lhi    = lane >> 4;
        const int bsub   = lane & 7;
        const int bhi8   = (lane >> 3) & 1;
        const int bnt    = lane >> 4;

        uint32_t kfb[2], vfb[2];
        {
            uint32_t b0 = smem_u32(smh);
            uint32_t off = ((bnt*8 + bsub) * LDKH + bhi8*8) * 2;
            kfb[0] = b0 + off;
            kfb[1] = b0 + KTILE_H*2 + off;
            vfb[0] = b0 + 2*KTILE_H*2 + off;
            vfb[1] = b0 + 3*KTILE_H*2 + off;
        }
        const uint32_t qfrag_addr = smem_u32(smh) + ((w*16 + lrow16) * LDKH + lhi*8) * 2;

        for (;;) {
            if (tid == 0) {
                unsigned it = atomicAdd(&g_ctr[1], 1);
                s_item = it;
                if (it < 1024) {
                    int hn = (it & 15) >> 1;
                    volatile unsigned* dg = (volatile unsigned*)g_done_g;
                    while (dg[hn] < 64u || dg[8 + hn] < 64u || dg[16 + hn] < 64u) {}
                }
            }
            __syncthreads();
            unsigned item = s_item;
            if (item >= 1024) break;
            const int h    = item & 15;
            const int bq   = item >> 4;          // b*16 + qb16
            const int b    = bq >> 4;
            const int qb16 = bq & 15;
            const int bh   = b * 16 + h;
            const int qb   = qb16 << 7;

            const __half* Qb  = g_Q  + (size_t)bh * Ssz * DKk;
            const __half* Kbp = g_K  + (size_t)bh * Ssz * DKk;
            const __half* Vtp = g_Vt + (size_t)bh * DKk * Ssz;

#pragma unroll
            for (int i = 0; i < 4; i++) {
                int idx = i * 256 + tid;
                int r = idx >> 3, c = idx & 7;
                cp_async16(smem_u32(&smh[r * LDKH + c * 8]),
                           Qb + (size_t)(qb + r) * DKk + c * 8);
            }
            CP_COMMIT();
            CP_WAIT0();
            __syncthreads();

            uint32_t qfr[4][4];
#pragma unroll
            for (int kk = 0; kk < 4; kk++)
                ldsm4(qfr[kk], qfrag_addr + kk*32);
            __syncthreads();

            auto issue_kv = [&](int kt, int bufi) {
                const int base = kt * 64;
                __half* kd = Kbuf[bufi];
                __half* vd = Vbuf[bufi];
#pragma unroll
                for (int i = 0; i < 2; i++) {
                    int idx = i * 256 + tid;
                    int r = idx >> 3, c = idx & 7;
                    cp_async16(smem_u32(&kd[r * LDKH + c * 8]),
                               Kbp + (size_t)(base + r) * DKk + c * 8);
                    cp_async16(smem_u32(&vd[r * LDKH + c * 8]),
                               Vtp + (size_t)r * Ssz + base + c * 8);
                }
                CP_COMMIT();
            };

            float oacc[8][4];
#pragma unroll
            for (int nt = 0; nt < 8; nt++)
#pragma unroll
                for (int k = 0; k < 4; k++) oacc[nt][k] = 0.f;
            float mA = -1e30f, mB = -1e30f, lA = 0.f, lB = 0.f;

            const int NT = Ssz / 64;
            issue_kv(0, 0);

            for (int kt = 0; kt < NT; kt++) {
                const int buf = kt & 1;
                CP_WAIT0();
                __syncthreads();
                if (kt + 1 < NT) issue_kv(kt + 1, buf ^ 1);

                float sacc[8][4];
#pragma unroll
                for (int nt = 0; nt < 8; nt++)
#pragma unroll
                    for (int k = 0; k < 4; k++) sacc[nt][k] = 0.f;
                uint32_t kb = kfb[buf];
#pragma unroll
                for (int ntp = 0; ntp < 4; ntp++) {
#pragma unroll
                    for (int kk = 0; kk < 4; kk++) {
                        uint32_t bb[4];
                        ldsm4(bb, kb + ntp * (16 * LDKH * 2) + kk * 32);
                        mma_f16(sacc[2*ntp],     qfr[kk], bb[0], bb[1]);
                        mma_f16(sacc[2*ntp + 1], qfr[kk], bb[2], bb[3]);
                    }
                }

                float mtA = -1e30f, mtB = -1e30f;
#pragma unroll
                for (int nt = 0; nt < 8; nt++) {
                    mtA = fmaxf(mtA, fmaxf(sacc[nt][0], sacc[nt][1]));
                    mtB = fmaxf(mtB, fmaxf(sacc[nt][2], sacc[nt][3]));
                }
                mtA = fmaxf(mtA, __shfl_xor_sync(0xffffffffu, mtA, 1));
                mtA = fmaxf(mtA, __shfl_xor_sync(0xffffffffu, mtA, 2));
                mtB = fmaxf(mtB, __shfl_xor_sync(0xffffffffu, mtB, 1));
                mtB = fmaxf(mtB, __shfl_xor_sync(0xffffffffu, mtB, 2));

                float corrA = 1.f, corrB = 1.f;
                if (mtA > mA || mtB > mB) {
                    float mnA = fmaxf(mA, mtA), mnB = fmaxf(mB, mtB);
                    corrA = exp2f(mA - mnA); corrB = exp2f(mB - mnB);
                    mA = mnA; mB = mnB;
#pragma unroll
                    for (int nt = 0; nt < 8; nt++) {
                        oacc[nt][0] *= corrA; oacc[nt][1] *= corrA;
                        oacc[nt][2] *= corrB; oacc[nt][3] *= corrB;
                    }
                }

                float sA = 0.f, sB = 0.f;
                uint32_t pA[8], pB[8];
#pragma unroll
                for (int nt = 0; nt < 8; nt++) {
                    float p0 = exp2f(sacc[nt][0] - mA);
                    float p1 = exp2f(sacc[nt][1] - mA);
                    float p2 = exp2f(sacc[nt][2] - mB);
                    float p3 = exp2f(sacc[nt][3] - mB);
                    sA += p0 + p1;
                    sB += p2 + p3;
                    pA[nt] = packh2(p0, p1);
                    pB[nt] = packh2(p2, p3);
                }
                sA += __shfl_xor_sync(0xffffffffu, sA, 1);
                sA += __shfl_xor_sync(0xffffffffu, sA, 2);
                sB += __shfl_xor_sync(0xffffffffu, sB, 1);
                sB += __shfl_xor_sync(0xffffffffu, sB, 2);
                lA = lA * corrA + sA;
                lB = lB * corrB + sB;

                uint32_t vb = vfb[buf];
#pragma unroll
                for (int ntp = 0; ntp < 4; ntp++) {
#pragma unroll
                    for (int kk = 0; kk < 4; kk++) {
                        uint32_t bb[4];
                        ldsm4(bb, vb + ntp * (16 * LDKH * 2) + kk * 32);
                        uint32_t afr[4] = { pA[2*kk], pB[2*kk], pA[2*kk + 1], pB[2*kk + 1] };
                        mma_f16(oacc[2*ntp],     afr, bb[0], bb[1]);
                        mma_f16(oacc[2*ntp + 1], afr, bb[2], bb[3]);
                    }
                }
            }

            const int g = lane >> 2, q = lane & 3;
            float invA = 1.f / lA, invB = 1.f / lB;
            int row0 = qb + w * 16 + g;
            int row1 = row0 + 8;
#pragma unroll
            for (int nt = 0; nt < 8; nt++) {
                int col = h * DKk + nt * 8 + q * 2;
                *(__half2*)&g_attn[(size_t)(b * Ssz + row0) * Dm + col] =
                    __floats2half2_rn(oacc[nt][0] * invA, oacc[nt][1] * invA);
                *(__half2*)&g_attn[(size_t)(b * Ssz + row1) * Dm + col] =
                    __floats2half2_rn(oacc[nt][2] * invB, oacc[nt][3] * invB);
            }
            __threadfence();
            __syncthreads();
            if (tid == 0) atomicAdd(&g_done_a[bq], 1);
        }
    }

    // ================= phase 3: output projection (mt-major) ===============
    for (;;) {
        if (tid == 0) {
            unsigned it = atomicAdd(&g_ctr[2], 1);
            s_item = it;
            if (it < 512) {
                int mt = it >> 3;
                volatile unsigned* da = (volatile unsigned*)g_done_a;
                while (da[mt] < 16u) {}
            }
        }
        __syncthreads();
        unsigned item = s_item;
        if (item >= 512) break;
        int bn = (item & 7) << 7;
        int bm = (item >> 3) << 7;
        gemm_tile(g_attn, g_Wo, bo, out, 0, bm, bn);
        __syncthreads();   // smem reuse guard before next item
    }
}

// ---------------------------------------------------------------------------
extern "C" void kernel_launch(void* const* d_in, const int* in_sizes, int n_in,
                              void* d_out, int out_size)
{
    const float* query = (const float*)d_in[0];
    const float* key_  = (const float*)d_in[1];
    const float* value = (const float*)d_in[2];
    const float* w_q   = (const float*)d_in[3];
    const float* b_q   = (const float*)d_in[4];
    const float* w_k   = (const float*)d_in[5];
    const float* b_k   = (const float*)d_in[6];
    const float* w_v   = (const float*)d_in[7];
    const float* b_v   = (const float*)d_in[8];
    const float* w_o   = (const float*)d_in[9];
    const float* b_o   = (const float*)d_in[10];
    float* out = (float*)d_out;

    cudaFuncSetAttribute(mega_kernel, cudaFuncAttributeMaxDynamicSharedMemorySize, MEGA_SMEM_BYTES);

    const int nX4 = Mrows * Dm / 4;
    const int nW4 = Dm * Dm / 4;

    // 1) conversions (conv_x3 also resets queue/dep counters)
    conv_x3<<<dim3(nX4 / 256, 1, 3), 256>>>(query, key_, value);
    conv_w4<<<dim3(nW4 / 256, 1, 4), 256>>>(w_q, w_k, w_v, w_o);

    // 2) fused qkv -> attention -> out-proj persistent megakernel
    mega_kernel<<<NPERS, 256, MEGA_SMEM_BYTES>>>(b_q, b_k, b_v, b_o, out);
}